// round 8
// baseline (speedup 1.0000x reference)
#include <cuda_runtime.h>
#include <cuda_bf16.h>
#include <math.h>
#include <stdlib.h>
#include <stdint.h>

#define NN 50000
#define NE 640000
#define NG 64
#define HD 128
#define INF 8
#define BN_EPS 1e-5f

// Best-effort eager module loading (kept from passing R5/R7).
__attribute__((constructor))
static void _set_eager_module_loading() {
    setenv("CUDA_MODULE_LOADING", "EAGER", 1);
}

// ---------------- scratch (static __device__; ~54 MB) ------------------------
__device__ float g_bufA[NN * HD];          // h1
__device__ float g_bufB[NN * HD];          // h2 (h3 never materialized)
__device__ int   g_deg[NN];
__device__ int   g_rowptr[NN + 1];
__device__ int   g_cursor[NN];
__device__ int   g_col[NE];
__device__ float g_pooled[NG * 384];

namespace {
struct TryEagerLoad {
    TryEagerLoad() { void* p = nullptr; cudaGetSymbolAddress(&p, g_bufA); }
};
static TryEagerLoad _try_eager_load;
}

// ---------------- mma.sync tf32 helpers (portable sm_80+) --------------------
__device__ __forceinline__ void mma_tf32(float* c,
        uint32_t a0, uint32_t a1, uint32_t a2, uint32_t a3,
        uint32_t b0, uint32_t b1) {
    asm volatile(
        "mma.sync.aligned.m16n8k8.row.col.f32.tf32.tf32.f32 "
        "{%0,%1,%2,%3}, {%4,%5,%6,%7}, {%8,%9}, {%0,%1,%2,%3};"
        : "+f"(c[0]), "+f"(c[1]), "+f"(c[2]), "+f"(c[3])
        : "r"(a0), "r"(a1), "r"(a2), "r"(a3), "r"(b0), "r"(b1));
}

// 3xTF32 split: x ~= hi + lo, both tf32-representable fp32 bit patterns.
__device__ __forceinline__ void split_tf32(float x, uint32_t& hi, uint32_t& lo) {
    asm("cvt.rna.tf32.f32 %0, %1;" : "=r"(hi) : "f"(x));
    float r = x - __uint_as_float(hi);
    asm("cvt.rna.tf32.f32 %0, %1;" : "=r"(lo) : "f"(r));
}

// ---------------- init + CSR ----------------
__global__ void zero_kernel() {
    int i = blockIdx.x * blockDim.x + threadIdx.x;
    if (i < NN) g_deg[i] = 0;
    if (i < NG * 384) g_pooled[i] = 0.f;
}

__global__ void count_kernel(const int* __restrict__ eidx) {
    int e = blockIdx.x * blockDim.x + threadIdx.x;
    if (e < NE) atomicAdd(&g_deg[eidx[NE + e]], 1);
}

// single-block shuffle scan over 50000 degrees -> rowptr, cursor(=exclusive)
__global__ void scan_kernel() {
    __shared__ int wsum[32];
    __shared__ int s_carry;
    int tid = threadIdx.x, lane = tid & 31, w = tid >> 5;
    if (tid == 0) { s_carry = 0; g_rowptr[0] = 0; }
    __syncthreads();
    for (int base = 0; base < NN; base += 1024) {
        int i = base + tid;
        int v = (i < NN) ? g_deg[i] : 0;
        int x = v;
        #pragma unroll
        for (int d = 1; d < 32; d <<= 1) {
            int t = __shfl_up_sync(~0u, x, d);
            if (lane >= d) x += t;
        }
        if (lane == 31) wsum[w] = x;
        __syncthreads();
        if (w == 0) {
            int y = wsum[lane];
            #pragma unroll
            for (int d = 1; d < 32; d <<= 1) {
                int t = __shfl_up_sync(~0u, y, d);
                if (lane >= d) y += t;
            }
            wsum[lane] = y;
        }
        __syncthreads();
        int inc = x + (w > 0 ? wsum[w - 1] : 0) + s_carry;
        if (i < NN) { g_rowptr[i + 1] = inc; g_cursor[i] = inc - v; }
        __syncthreads();
        if (tid == 1023) s_carry = inc;
        __syncthreads();
    }
}

__global__ void fill_kernel(const int* __restrict__ eidx) {
    int e = blockIdx.x * blockDim.x + threadIdx.x;
    if (e < NE) {
        int src = eidx[e];
        int dst = eidx[NE + e];
        g_col[atomicAdd(&g_cursor[dst], 1)] = src;
    }
}

// ---------------- fused GIN layer (mma.sync tf32x3, pre-split weights) -------
// 512 threads; 128-node tile; 16 warps each own a 16x64 output block.
// smem regions (all stride 132):
//   sWhi[128][132], sWlo[128][132]  : W1 hi/lo, later overwritten by W2 hi/lo
//   sIO [128][132]                  : gather input -> stage-A out -> stage-B out
template <int FIN, int SLICE, bool WRITE>
__global__ void __launch_bounds__(512, 1)
gin_layer(const float* __restrict__ src,
          const float* __restrict__ W1, const float* __restrict__ b1,
          const float* __restrict__ W2, const float* __restrict__ b2,
          const int* __restrict__ batch,
          float* __restrict__ out, int n) {
    extern __shared__ float smem[];
    float* sWhi = smem;                     // 128*132
    float* sWlo = sWhi + 128 * 132;         // 128*132
    float* sIO  = sWlo + 128 * 132;         // 128*132
    float* b1s  = sIO + 128 * 132;
    float* b2s  = b1s + 128;
    int*   sBatch = (int*)(b2s + 128);

    const int tid  = threadIdx.x;
    const int lane = tid & 31;
    const int wid  = tid >> 5;              // 16 warps
    const int node0 = blockIdx.x * 128;

    // load + SPLIT W1 [FIN][128] into sWhi/sWlo
    for (int i = tid; i < FIN * 32; i += 512) {
        int k = i >> 5, c = (i & 31) * 4;
        float4 w = ((const float4*)W1)[i];
        uint32_t h0, l0, h1, l1, h2, l2, h3, l3;
        split_tf32(w.x, h0, l0); split_tf32(w.y, h1, l1);
        split_tf32(w.z, h2, l2); split_tf32(w.w, h3, l3);
        float4 vh = make_float4(__uint_as_float(h0), __uint_as_float(h1),
                                __uint_as_float(h2), __uint_as_float(h3));
        float4 vl = make_float4(__uint_as_float(l0), __uint_as_float(l1),
                                __uint_as_float(l2), __uint_as_float(l3));
        *(float4*)&sWhi[k * 132 + c] = vh;
        *(float4*)&sWlo[k * 132 + c] = vl;
    }
    if (tid < 128) {
        b1s[tid] = b1[tid];
        b2s[tid] = b2[tid];
        int node = node0 + tid;
        sBatch[tid] = batch[node < n ? node : (n - 1)];
    }

    // gather: sIO[r][:] = src[node] + sum_neighbors
    if (FIN == 128) {
        const float4* src4 = (const float4*)src;
        for (int r = wid; r < 128; r += 16) {
            int node = node0 + r;
            float4 acc = make_float4(0.f, 0.f, 0.f, 0.f);
            if (node < n) {
                acc = src4[node * 32 + lane];
                int s = g_rowptr[node], e = g_rowptr[node + 1];
                #pragma unroll 4
                for (int j = s; j < e; j++) {
                    float4 v = src4[g_col[j] * 32 + lane];
                    acc.x += v.x; acc.y += v.y; acc.z += v.z; acc.w += v.w;
                }
            }
            *(float4*)&sIO[r * 132 + lane * 4] = acc;
        }
    } else {  // FIN == 8
        const float4* src4 = (const float4*)src;
        for (int r = wid; r < 128; r += 16) {
            if (lane < 2) {
                int node = node0 + r;
                float4 acc = make_float4(0.f, 0.f, 0.f, 0.f);
                if (node < n) {
                    acc = src4[node * 2 + lane];
                    int s = g_rowptr[node], e = g_rowptr[node + 1];
                    #pragma unroll 4
                    for (int j = s; j < e; j++) {
                        float4 v = src4[g_col[j] * 2 + lane];
                        acc.x += v.x; acc.y += v.y; acc.z += v.z; acc.w += v.w;
                    }
                }
                *(float4*)&sIO[r * 132 + lane * 4] = acc;
            }
        }
    }
    __syncthreads();

    // warp tiling: rows [row0, row0+16), cols [col0, col0+64)
    const int row0 = (wid >> 1) * 16;
    const int col0 = (wid & 1) * 64;
    const int qr = lane >> 2;   // 0..7
    const int qc = lane & 3;    // 0..3

    float acc[8][4];

    // ---- stage A: acc = sIO @ W1 + b1 (3xTF32) ----
    #pragma unroll
    for (int nt = 0; nt < 8; nt++) {
        int c = col0 + nt * 8 + 2 * qc;
        acc[nt][0] = b1s[c];     acc[nt][1] = b1s[c + 1];
        acc[nt][2] = b1s[c];     acc[nt][3] = b1s[c + 1];
    }
    #pragma unroll
    for (int ks = 0; ks < FIN / 8; ks++) {
        int k0 = ks * 8;
        float a0f = sIO[(row0 + qr)     * 132 + k0 + qc];
        float a1f = sIO[(row0 + qr + 8) * 132 + k0 + qc];
        float a2f = sIO[(row0 + qr)     * 132 + k0 + qc + 4];
        float a3f = sIO[(row0 + qr + 8) * 132 + k0 + qc + 4];
        uint32_t ah0, al0, ah1, al1, ah2, al2, ah3, al3;
        split_tf32(a0f, ah0, al0); split_tf32(a1f, ah1, al1);
        split_tf32(a2f, ah2, al2); split_tf32(a3f, ah3, al3);
        #pragma unroll
        for (int nt = 0; nt < 8; nt++) {
            int bn = col0 + nt * 8 + qr;
            uint32_t bh0 = __float_as_uint(sWhi[(k0 + qc)     * 132 + bn]);
            uint32_t bl0 = __float_as_uint(sWlo[(k0 + qc)     * 132 + bn]);
            uint32_t bh1 = __float_as_uint(sWhi[(k0 + qc + 4) * 132 + bn]);
            uint32_t bl1 = __float_as_uint(sWlo[(k0 + qc + 4) * 132 + bn]);
            mma_tf32(acc[nt], ah0, ah1, ah2, ah3, bh0, bh1);
            mma_tf32(acc[nt], ah0, ah1, ah2, ah3, bl0, bl1);
            mma_tf32(acc[nt], al0, al1, al2, al3, bh0, bh1);
        }
    }
    __syncthreads();  // all stage-A reads of sIO and W1 regions complete

    // write stage-A relu output back into sIO (own rows, own col half)
    #pragma unroll
    for (int nt = 0; nt < 8; nt++) {
        int c = col0 + nt * 8 + 2 * qc;
        int r = row0 + qr;
        sIO[r * 132 + c]           = fmaxf(acc[nt][0], 0.f);
        sIO[r * 132 + c + 1]       = fmaxf(acc[nt][1], 0.f);
        sIO[(r + 8) * 132 + c]     = fmaxf(acc[nt][2], 0.f);
        sIO[(r + 8) * 132 + c + 1] = fmaxf(acc[nt][3], 0.f);
    }
    // load + SPLIT W2 [128][128] over W1 regions (concurrent with writes above)
    for (int i = tid; i < 4096; i += 512) {
        int k = i >> 5, c = (i & 31) * 4;
        float4 w = ((const float4*)W2)[i];
        uint32_t h0, l0, h1, l1, h2, l2, h3, l3;
        split_tf32(w.x, h0, l0); split_tf32(w.y, h1, l1);
        split_tf32(w.z, h2, l2); split_tf32(w.w, h3, l3);
        float4 vh = make_float4(__uint_as_float(h0), __uint_as_float(h1),
                                __uint_as_float(h2), __uint_as_float(h3));
        float4 vl = make_float4(__uint_as_float(l0), __uint_as_float(l1),
                                __uint_as_float(l2), __uint_as_float(l3));
        *(float4*)&sWhi[k * 132 + c] = vh;
        *(float4*)&sWlo[k * 132 + c] = vl;
    }
    __syncthreads();

    // ---- stage B: acc = sIO @ W2 + b2 (3xTF32) ----
    #pragma unroll
    for (int nt = 0; nt < 8; nt++) {
        int c = col0 + nt * 8 + 2 * qc;
        acc[nt][0] = b2s[c];     acc[nt][1] = b2s[c + 1];
        acc[nt][2] = b2s[c];     acc[nt][3] = b2s[c + 1];
    }
    #pragma unroll
    for (int ks = 0; ks < 16; ks++) {
        int k0 = ks * 8;
        float a0f = sIO[(row0 + qr)     * 132 + k0 + qc];
        float a1f = sIO[(row0 + qr + 8) * 132 + k0 + qc];
        float a2f = sIO[(row0 + qr)     * 132 + k0 + qc + 4];
        float a3f = sIO[(row0 + qr + 8) * 132 + k0 + qc + 4];
        uint32_t ah0, al0, ah1, al1, ah2, al2, ah3, al3;
        split_tf32(a0f, ah0, al0); split_tf32(a1f, ah1, al1);
        split_tf32(a2f, ah2, al2); split_tf32(a3f, ah3, al3);
        #pragma unroll
        for (int nt = 0; nt < 8; nt++) {
            int bn = col0 + nt * 8 + qr;
            uint32_t bh0 = __float_as_uint(sWhi[(k0 + qc)     * 132 + bn]);
            uint32_t bl0 = __float_as_uint(sWlo[(k0 + qc)     * 132 + bn]);
            uint32_t bh1 = __float_as_uint(sWhi[(k0 + qc + 4) * 132 + bn]);
            uint32_t bl1 = __float_as_uint(sWlo[(k0 + qc + 4) * 132 + bn]);
            mma_tf32(acc[nt], ah0, ah1, ah2, ah3, bh0, bh1);
            mma_tf32(acc[nt], ah0, ah1, ah2, ah3, bl0, bl1);
            mma_tf32(acc[nt], al0, al1, al2, al3, bh0, bh1);
        }
    }
    __syncthreads();  // all stage-B reads of sIO complete before overwrite

    // epilogue: relu, zero invalid rows, stash final tile in sIO
    {
        int rA = row0 + qr, rB = row0 + qr + 8;
        bool vA = (node0 + rA) < n, vB = (node0 + rB) < n;
        #pragma unroll
        for (int nt = 0; nt < 8; nt++) {
            int c = col0 + nt * 8 + 2 * qc;
            sIO[rA * 132 + c]     = vA ? fmaxf(acc[nt][0], 0.f) : 0.f;
            sIO[rA * 132 + c + 1] = vA ? fmaxf(acc[nt][1], 0.f) : 0.f;
            sIO[rB * 132 + c]     = vB ? fmaxf(acc[nt][2], 0.f) : 0.f;
            sIO[rB * 132 + c + 1] = vB ? fmaxf(acc[nt][3], 0.f) : 0.f;
        }
    }
    __syncthreads();

    // pooling: thread f sums its feature column over sorted-batch segments
    if (tid < 128) {
        int f = tid;
        float pacc = sIO[f];
        int curg = sBatch[0];
        for (int r = 1; r < 128; r++) {
            int g = sBatch[r];
            if (g != curg) {
                atomicAdd(&g_pooled[curg * 384 + SLICE + f], pacc);
                pacc = 0.f;
                curg = g;
            }
            pacc += sIO[r * 132 + f];
        }
        atomicAdd(&g_pooled[curg * 384 + SLICE + f], pacc);
    }

    // coalesced float4 writeback
    if (WRITE) {
        float4* out4 = (float4*)out;
        for (int idx = tid; idx < 128 * 32; idx += 512) {
            int r = idx >> 5, c4 = idx & 31;
            int node = node0 + r;
            if (node < n)
                out4[node * 32 + c4] = *(float4*)&sIO[r * 132 + c4 * 4];
        }
    }
}

// ---------------- classifier ----------------
__global__ void cls_kernel(const float* __restrict__ W1, const float* __restrict__ b1,
                           const float* __restrict__ gamma, const float* __restrict__ beta,
                           const float* __restrict__ mean, const float* __restrict__ var,
                           const float* __restrict__ W2, const float* __restrict__ b2,
                           float* __restrict__ out) {
    __shared__ float sp[384];
    __shared__ float sz[256];
    int g = blockIdx.x;
    int tid = threadIdx.x;  // 0..255
    for (int i = tid; i < 384; i += 256) sp[i] = g_pooled[g * 384 + i];
    __syncthreads();
    float acc = b1[tid];
    #pragma unroll 8
    for (int k = 0; k < 384; k++) acc += sp[k] * W1[k * 256 + tid];
    float z = (acc - mean[tid]) * rsqrtf(var[tid] + BN_EPS) * gamma[tid] + beta[tid];
    sz[tid] = fmaxf(z, 0.f);
    __syncthreads();
    if (tid < 4) {
        float o = b2[tid];
        #pragma unroll 8
        for (int k = 0; k < 256; k++) o += sz[k] * W2[k * 4 + tid];
        out[g * 4 + tid] = o;
    }
}

// ---------------- launch ----------------
extern "C" void kernel_launch(void* const* d_in, const int* in_sizes, int n_in,
                              void* d_out, int out_size) {
    const float* x     = (const float*)d_in[0];
    const int*   eidx  = (const int*)d_in[1];
    const int*   batch = (const int*)d_in[2];
    const float* l1_W1 = (const float*)d_in[3];
    const float* l1_b1 = (const float*)d_in[4];
    const float* l1_W2 = (const float*)d_in[5];
    const float* l1_b2 = (const float*)d_in[6];
    const float* l2_W1 = (const float*)d_in[7];
    const float* l2_b1 = (const float*)d_in[8];
    const float* l2_W2 = (const float*)d_in[9];
    const float* l2_b2 = (const float*)d_in[10];
    const float* l3_W1 = (const float*)d_in[11];
    const float* l3_b1 = (const float*)d_in[12];
    const float* l3_W2 = (const float*)d_in[13];
    const float* l3_b2 = (const float*)d_in[14];
    const float* c_W1  = (const float*)d_in[15];
    const float* c_b1  = (const float*)d_in[16];
    const float* bn_g  = (const float*)d_in[17];
    const float* bn_b  = (const float*)d_in[18];
    const float* bn_m  = (const float*)d_in[19];
    const float* bn_v  = (const float*)d_in[20];
    const float* c_W2  = (const float*)d_in[21];
    const float* c_b2  = (const float*)d_in[22];
    float* out = (float*)d_out;

    // smem: 3 * 128*132 floats + b1s/b2s + batch
    const int SMEM = (3 * 128 * 132 + 256) * 4 + 512;  // 204288
    cudaFuncSetAttribute(gin_layer<8, 0, true>,
                         cudaFuncAttributeMaxDynamicSharedMemorySize, SMEM);
    cudaFuncSetAttribute(gin_layer<128, 128, true>,
                         cudaFuncAttributeMaxDynamicSharedMemorySize, SMEM);
    cudaFuncSetAttribute(gin_layer<128, 256, false>,
                         cudaFuncAttributeMaxDynamicSharedMemorySize, SMEM);

    float *bufA, *bufB;
    cudaGetSymbolAddress((void**)&bufA, g_bufA);
    cudaGetSymbolAddress((void**)&bufB, g_bufB);

    // init + CSR
    zero_kernel<<<(NN + 255) / 256, 256>>>();
    count_kernel<<<(NE + 255) / 256, 256>>>(eidx);
    scan_kernel<<<1, 1024>>>();
    fill_kernel<<<(NE + 255) / 256, 256>>>(eidx);

    const int GRID = (NN + 127) / 128;  // 391

    gin_layer<8, 0, true><<<GRID, 512, SMEM>>>(
        x, l1_W1, l1_b1, l1_W2, l1_b2, batch, bufA, NN);
    gin_layer<128, 128, true><<<GRID, 512, SMEM>>>(
        bufA, l2_W1, l2_b1, l2_W2, l2_b2, batch, bufB, NN);
    gin_layer<128, 256, false><<<GRID, 512, SMEM>>>(
        bufB, l3_W1, l3_b1, l3_W2, l3_b2, batch, nullptr, NN);

    cls_kernel<<<NG, 256>>>(c_W1, c_b1, bn_g, bn_b, bn_m, bn_v, c_W2, c_b2, out);
}

// round 9
// speedup vs baseline: 1.0295x; 1.0295x over previous
#include <cuda_runtime.h>
#include <cuda_bf16.h>
#include <math.h>
#include <stdlib.h>
#include <stdint.h>

#define NN 50000
#define NE 640000
#define NG 64
#define HD 128
#define INF 8
#define BN_EPS 1e-5f
#define TILE 64

// Best-effort eager module loading (kept from passing rounds).
__attribute__((constructor))
static void _set_eager_module_loading() {
    setenv("CUDA_MODULE_LOADING", "EAGER", 1);
}

// ---------------- scratch (static __device__; ~54 MB) ------------------------
__device__ float g_bufA[NN * HD];          // h1
__device__ float g_bufB[NN * HD];          // h2 (h3 never materialized)
__device__ int   g_deg[NN];
__device__ int   g_rowptr[NN + 1];
__device__ int   g_cursor[NN];
__device__ int   g_col[NE];
__device__ float g_pooled[NG * 384];

namespace {
struct TryEagerLoad {
    TryEagerLoad() { void* p = nullptr; cudaGetSymbolAddress(&p, g_bufA); }
};
static TryEagerLoad _try_eager_load;
}

// ---------------- mma.sync tf32 helpers (portable sm_80+) --------------------
__device__ __forceinline__ void mma_tf32(float* c,
        uint32_t a0, uint32_t a1, uint32_t a2, uint32_t a3,
        uint32_t b0, uint32_t b1) {
    asm volatile(
        "mma.sync.aligned.m16n8k8.row.col.f32.tf32.tf32.f32 "
        "{%0,%1,%2,%3}, {%4,%5,%6,%7}, {%8,%9}, {%0,%1,%2,%3};"
        : "+f"(c[0]), "+f"(c[1]), "+f"(c[2]), "+f"(c[3])
        : "r"(a0), "r"(a1), "r"(a2), "r"(a3), "r"(b0), "r"(b1));
}

// 3xTF32 split: x ~= hi + lo, both tf32-representable fp32 bit patterns.
__device__ __forceinline__ void split_tf32(float x, uint32_t& hi, uint32_t& lo) {
    asm("cvt.rna.tf32.f32 %0, %1;" : "=r"(hi) : "f"(x));
    float r = x - __uint_as_float(hi);
    asm("cvt.rna.tf32.f32 %0, %1;" : "=r"(lo) : "f"(r));
}

// ---------------- init + CSR ----------------
__global__ void zero_kernel() {
    int i = blockIdx.x * blockDim.x + threadIdx.x;
    if (i < NN) g_deg[i] = 0;
    if (i < NG * 384) g_pooled[i] = 0.f;
}

__global__ void count_kernel(const int* __restrict__ eidx) {
    int e = blockIdx.x * blockDim.x + threadIdx.x;
    if (e < NE) atomicAdd(&g_deg[eidx[NE + e]], 1);
}

// single-block shuffle scan over 50000 degrees -> rowptr, cursor(=exclusive)
__global__ void scan_kernel() {
    __shared__ int wsum[32];
    __shared__ int s_carry;
    int tid = threadIdx.x, lane = tid & 31, w = tid >> 5;
    if (tid == 0) { s_carry = 0; g_rowptr[0] = 0; }
    __syncthreads();
    for (int base = 0; base < NN; base += 1024) {
        int i = base + tid;
        int v = (i < NN) ? g_deg[i] : 0;
        int x = v;
        #pragma unroll
        for (int d = 1; d < 32; d <<= 1) {
            int t = __shfl_up_sync(~0u, x, d);
            if (lane >= d) x += t;
        }
        if (lane == 31) wsum[w] = x;
        __syncthreads();
        if (w == 0) {
            int y = wsum[lane];
            #pragma unroll
            for (int d = 1; d < 32; d <<= 1) {
                int t = __shfl_up_sync(~0u, y, d);
                if (lane >= d) y += t;
            }
            wsum[lane] = y;
        }
        __syncthreads();
        int inc = x + (w > 0 ? wsum[w - 1] : 0) + s_carry;
        if (i < NN) { g_rowptr[i + 1] = inc; g_cursor[i] = inc - v; }
        __syncthreads();
        if (tid == 1023) s_carry = inc;
        __syncthreads();
    }
}

__global__ void fill_kernel(const int* __restrict__ eidx) {
    int e = blockIdx.x * blockDim.x + threadIdx.x;
    if (e < NE) {
        int src = eidx[e];
        int dst = eidx[NE + e];
        g_col[atomicAdd(&g_cursor[dst], 1)] = src;
    }
}

// ---------------- fused GIN layer (mma.sync tf32x3, 64-row tiles) ------------
// 256 threads; 64-node tile; 8 warps each own a 16x64 output block.
// smem: sW[FIN][132] (W1, later W2) | sIO[64][132] | b1s | b2s | batch
// ~102.7 KB for FIN=128 -> 2 CTAs/SM; ~39 KB for FIN=8 -> 5 CTAs/SM.
template <int FIN, int SLICE, bool WRITE>
__global__ void __launch_bounds__(256, 2)
gin_layer(const float* __restrict__ src,
          const float* __restrict__ W1, const float* __restrict__ b1,
          const float* __restrict__ W2, const float* __restrict__ b2,
          const int* __restrict__ batch,
          float* __restrict__ out, int n) {
    constexpr int WROWS = (FIN == 128) ? 128 : 8;   // rows of sW region
    extern __shared__ float smem[];
    float* sW  = smem;                       // max(FIN,128 for W2)... see below
    // NOTE: W2 is 128x128, so the sW region must always hold 128 rows.
    float* sIO = sW + 128 * 132;             // 64*132
    float* b1s = sIO + TILE * 132;
    float* b2s = b1s + 128;
    int*   sBatch = (int*)(b2s + 128);
    (void)WROWS;

    const int tid  = threadIdx.x;
    const int lane = tid & 31;
    const int wid  = tid >> 5;               // 8 warps
    const int node0 = blockIdx.x * TILE;

    // load W1 [FIN][128] -> sW (stride 132)
    for (int i = tid; i < FIN * 32; i += 256) {
        int k = i >> 5, c = i & 31;
        *(float4*)&sW[k * 132 + c * 4] = ((const float4*)W1)[i];
    }
    if (tid < 128) {
        b1s[tid] = b1[tid];
        b2s[tid] = b2[tid];
    }
    if (tid < TILE) {
        int node = node0 + tid;
        sBatch[tid] = batch[node < n ? node : (n - 1)];
    }

    // gather: sIO[r][:] = src[node] + sum_neighbors
    if (FIN == 128) {
        const float4* src4 = (const float4*)src;
        for (int r = wid; r < TILE; r += 8) {
            int node = node0 + r;
            float4 acc = make_float4(0.f, 0.f, 0.f, 0.f);
            if (node < n) {
                acc = src4[node * 32 + lane];
                int s = g_rowptr[node], e = g_rowptr[node + 1];
                #pragma unroll 4
                for (int j = s; j < e; j++) {
                    float4 v = src4[g_col[j] * 32 + lane];
                    acc.x += v.x; acc.y += v.y; acc.z += v.z; acc.w += v.w;
                }
            }
            *(float4*)&sIO[r * 132 + lane * 4] = acc;
        }
    } else {  // FIN == 8
        const float4* src4 = (const float4*)src;
        for (int r = wid; r < TILE; r += 8) {
            if (lane < 2) {
                int node = node0 + r;
                float4 acc = make_float4(0.f, 0.f, 0.f, 0.f);
                if (node < n) {
                    acc = src4[node * 2 + lane];
                    int s = g_rowptr[node], e = g_rowptr[node + 1];
                    #pragma unroll 4
                    for (int j = s; j < e; j++) {
                        float4 v = src4[g_col[j] * 2 + lane];
                        acc.x += v.x; acc.y += v.y; acc.z += v.z; acc.w += v.w;
                    }
                }
                *(float4*)&sIO[r * 132 + lane * 4] = acc;
            }
        }
    }
    __syncthreads();

    // warp tiling: rows [row0, row0+16), cols [col0, col0+64)
    const int row0 = (wid >> 1) * 16;        // 0,16,32,48
    const int col0 = (wid & 1) * 64;
    const int qr = lane >> 2;   // 0..7
    const int qc = lane & 3;    // 0..3

    float acc[8][4];

    // ---- stage A: acc = sIO @ W1 + b1 (3xTF32, on-the-fly splits) ----
    #pragma unroll
    for (int nt = 0; nt < 8; nt++) {
        int c = col0 + nt * 8 + 2 * qc;
        acc[nt][0] = b1s[c];     acc[nt][1] = b1s[c + 1];
        acc[nt][2] = b1s[c];     acc[nt][3] = b1s[c + 1];
    }
    #pragma unroll
    for (int ks = 0; ks < FIN / 8; ks++) {
        int k0 = ks * 8;
        float a0f = sIO[(row0 + qr)     * 132 + k0 + qc];
        float a1f = sIO[(row0 + qr + 8) * 132 + k0 + qc];
        float a2f = sIO[(row0 + qr)     * 132 + k0 + qc + 4];
        float a3f = sIO[(row0 + qr + 8) * 132 + k0 + qc + 4];
        uint32_t ah0, al0, ah1, al1, ah2, al2, ah3, al3;
        split_tf32(a0f, ah0, al0); split_tf32(a1f, ah1, al1);
        split_tf32(a2f, ah2, al2); split_tf32(a3f, ah3, al3);
        #pragma unroll
        for (int nt = 0; nt < 8; nt++) {
            int bn = col0 + nt * 8 + qr;
            float b0f = sW[(k0 + qc)     * 132 + bn];
            float b1f = sW[(k0 + qc + 4) * 132 + bn];
            uint32_t bh0, bl0, bh1, bl1;
            split_tf32(b0f, bh0, bl0); split_tf32(b1f, bh1, bl1);
            mma_tf32(acc[nt], ah0, ah1, ah2, ah3, bh0, bh1);
            mma_tf32(acc[nt], ah0, ah1, ah2, ah3, bl0, bl1);
            mma_tf32(acc[nt], al0, al1, al2, al3, bh0, bh1);
        }
    }
    __syncthreads();  // all stage-A reads of sIO and sW complete

    // write stage-A relu output back into sIO; load W2 over sW
    #pragma unroll
    for (int nt = 0; nt < 8; nt++) {
        int c = col0 + nt * 8 + 2 * qc;
        int r = row0 + qr;
        sIO[r * 132 + c]           = fmaxf(acc[nt][0], 0.f);
        sIO[r * 132 + c + 1]       = fmaxf(acc[nt][1], 0.f);
        sIO[(r + 8) * 132 + c]     = fmaxf(acc[nt][2], 0.f);
        sIO[(r + 8) * 132 + c + 1] = fmaxf(acc[nt][3], 0.f);
    }
    for (int i = tid; i < 4096; i += 256) {
        int k = i >> 5, c = i & 31;
        *(float4*)&sW[k * 132 + c * 4] = ((const float4*)W2)[i];
    }
    __syncthreads();

    // ---- stage B: acc = sIO @ W2 + b2 (3xTF32) ----
    #pragma unroll
    for (int nt = 0; nt < 8; nt++) {
        int c = col0 + nt * 8 + 2 * qc;
        acc[nt][0] = b2s[c];     acc[nt][1] = b2s[c + 1];
        acc[nt][2] = b2s[c];     acc[nt][3] = b2s[c + 1];
    }
    #pragma unroll
    for (int ks = 0; ks < 16; ks++) {
        int k0 = ks * 8;
        float a0f = sIO[(row0 + qr)     * 132 + k0 + qc];
        float a1f = sIO[(row0 + qr + 8) * 132 + k0 + qc];
        float a2f = sIO[(row0 + qr)     * 132 + k0 + qc + 4];
        float a3f = sIO[(row0 + qr + 8) * 132 + k0 + qc + 4];
        uint32_t ah0, al0, ah1, al1, ah2, al2, ah3, al3;
        split_tf32(a0f, ah0, al0); split_tf32(a1f, ah1, al1);
        split_tf32(a2f, ah2, al2); split_tf32(a3f, ah3, al3);
        #pragma unroll
        for (int nt = 0; nt < 8; nt++) {
            int bn = col0 + nt * 8 + qr;
            float b0f = sW[(k0 + qc)     * 132 + bn];
            float b1f = sW[(k0 + qc + 4) * 132 + bn];
            uint32_t bh0, bl0, bh1, bl1;
            split_tf32(b0f, bh0, bl0); split_tf32(b1f, bh1, bl1);
            mma_tf32(acc[nt], ah0, ah1, ah2, ah3, bh0, bh1);
            mma_tf32(acc[nt], ah0, ah1, ah2, ah3, bl0, bl1);
            mma_tf32(acc[nt], al0, al1, al2, al3, bh0, bh1);
        }
    }
    __syncthreads();  // all stage-B reads of sIO complete before overwrite

    // epilogue: relu, zero invalid rows, stash final tile in sIO
    {
        int rA = row0 + qr, rB = row0 + qr + 8;
        bool vA = (node0 + rA) < n, vB = (node0 + rB) < n;
        #pragma unroll
        for (int nt = 0; nt < 8; nt++) {
            int c = col0 + nt * 8 + 2 * qc;
            sIO[rA * 132 + c]     = vA ? fmaxf(acc[nt][0], 0.f) : 0.f;
            sIO[rA * 132 + c + 1] = vA ? fmaxf(acc[nt][1], 0.f) : 0.f;
            sIO[rB * 132 + c]     = vB ? fmaxf(acc[nt][2], 0.f) : 0.f;
            sIO[rB * 132 + c + 1] = vB ? fmaxf(acc[nt][3], 0.f) : 0.f;
        }
    }
    __syncthreads();

    // pooling: thread f sums its feature column over sorted-batch segments
    if (tid < 128) {
        int f = tid;
        float pacc = sIO[f];
        int curg = sBatch[0];
        for (int r = 1; r < TILE; r++) {
            int g = sBatch[r];
            if (g != curg) {
                atomicAdd(&g_pooled[curg * 384 + SLICE + f], pacc);
                pacc = 0.f;
                curg = g;
            }
            pacc += sIO[r * 132 + f];
        }
        atomicAdd(&g_pooled[curg * 384 + SLICE + f], pacc);
    }

    // coalesced float4 writeback
    if (WRITE) {
        float4* out4 = (float4*)out;
        for (int idx = tid; idx < TILE * 32; idx += 256) {
            int r = idx >> 5, c4 = idx & 31;
            int node = node0 + r;
            if (node < n)
                out4[node * 32 + c4] = *(float4*)&sIO[r * 132 + c4 * 4];
        }
    }
}

// ---------------- classifier ----------------
__global__ void cls_kernel(const float* __restrict__ W1, const float* __restrict__ b1,
                           const float* __restrict__ gamma, const float* __restrict__ beta,
                           const float* __restrict__ mean, const float* __restrict__ var,
                           const float* __restrict__ W2, const float* __restrict__ b2,
                           float* __restrict__ out) {
    __shared__ float sp[384];
    __shared__ float sz[256];
    int g = blockIdx.x;
    int tid = threadIdx.x;  // 0..255
    for (int i = tid; i < 384; i += 256) sp[i] = g_pooled[g * 384 + i];
    __syncthreads();
    float acc = b1[tid];
    #pragma unroll 8
    for (int k = 0; k < 384; k++) acc += sp[k] * W1[k * 256 + tid];
    float z = (acc - mean[tid]) * rsqrtf(var[tid] + BN_EPS) * gamma[tid] + beta[tid];
    sz[tid] = fmaxf(z, 0.f);
    __syncthreads();
    if (tid < 4) {
        float o = b2[tid];
        #pragma unroll 8
        for (int k = 0; k < 256; k++) o += sz[k] * W2[k * 4 + tid];
        out[g * 4 + tid] = o;
    }
}

// ---------------- launch ----------------
extern "C" void kernel_launch(void* const* d_in, const int* in_sizes, int n_in,
                              void* d_out, int out_size) {
    const float* x     = (const float*)d_in[0];
    const int*   eidx  = (const int*)d_in[1];
    const int*   batch = (const int*)d_in[2];
    const float* l1_W1 = (const float*)d_in[3];
    const float* l1_b1 = (const float*)d_in[4];
    const float* l1_W2 = (const float*)d_in[5];
    const float* l1_b2 = (const float*)d_in[6];
    const float* l2_W1 = (const float*)d_in[7];
    const float* l2_b1 = (const float*)d_in[8];
    const float* l2_W2 = (const float*)d_in[9];
    const float* l2_b2 = (const float*)d_in[10];
    const float* l3_W1 = (const float*)d_in[11];
    const float* l3_b1 = (const float*)d_in[12];
    const float* l3_W2 = (const float*)d_in[13];
    const float* l3_b2 = (const float*)d_in[14];
    const float* c_W1  = (const float*)d_in[15];
    const float* c_b1  = (const float*)d_in[16];
    const float* bn_g  = (const float*)d_in[17];
    const float* bn_b  = (const float*)d_in[18];
    const float* bn_m  = (const float*)d_in[19];
    const float* bn_v  = (const float*)d_in[20];
    const float* c_W2  = (const float*)d_in[21];
    const float* c_b2  = (const float*)d_in[22];
    float* out = (float*)d_out;

    // smem: sW(128*132) + sIO(64*132) + b1s/b2s(256) + batch(64)
    const int SMEM = (128 * 132 + TILE * 132 + 256 + TILE) * 4 + 256;  // ~102.9 KB
    cudaFuncSetAttribute(gin_layer<8, 0, true>,
                         cudaFuncAttributeMaxDynamicSharedMemorySize, SMEM);
    cudaFuncSetAttribute(gin_layer<128, 128, true>,
                         cudaFuncAttributeMaxDynamicSharedMemorySize, SMEM);
    cudaFuncSetAttribute(gin_layer<128, 256, false>,
                         cudaFuncAttributeMaxDynamicSharedMemorySize, SMEM);

    float *bufA, *bufB;
    cudaGetSymbolAddress((void**)&bufA, g_bufA);
    cudaGetSymbolAddress((void**)&bufB, g_bufB);

    // init + CSR
    zero_kernel<<<(NN + 255) / 256, 256>>>();
    count_kernel<<<(NE + 255) / 256, 256>>>(eidx);
    scan_kernel<<<1, 1024>>>();
    fill_kernel<<<(NE + 255) / 256, 256>>>(eidx);

    const int GRID = (NN + TILE - 1) / TILE;  // 782

    gin_layer<8, 0, true><<<GRID, 256, SMEM>>>(
        x, l1_W1, l1_b1, l1_W2, l1_b2, batch, bufA, NN);
    gin_layer<128, 128, true><<<GRID, 256, SMEM>>>(
        bufA, l2_W1, l2_b1, l2_W2, l2_b2, batch, bufB, NN);
    gin_layer<128, 256, false><<<GRID, 256, SMEM>>>(
        bufB, l3_W1, l3_b1, l3_W2, l3_b2, batch, nullptr, NN);

    cls_kernel<<<NG, 256>>>(c_W1, c_b1, bn_g, bn_b, bn_m, bn_v, c_W2, c_b2, out);
}